// round 4
// baseline (speedup 1.0000x reference)
#include <cuda_runtime.h>
#include <cuda_fp16.h>
#include <cstdint>

#define NNODE 100000
#define NEDGE 3200000
#define FIN   128
#define HDIM  32
#define MHDIM 64
#define NCLS  10
#define NGRAPH 64
#define NBLK  ((NNODE + 255) / 256)   // 391

// ---------------- device scratch (static, no allocation) ----------------
__device__ float   g_deg[NNODE];
__device__ float   g_dinv[NNODE];
__device__ int     g_cntD[NNODE];
__device__ int     g_ptrD[NNODE + 1];
__device__ int2    g_eD[NEDGE];          // (src, weight-bits) packed
__device__ int     g_blkSum[NBLK];
__device__ int     g_blkOff[NBLK];
__device__ __half2 g_tA[(size_t)NNODE * 16];   // feature tables, fp16, double-buffered
__device__ __half2 g_tB[(size_t)NNODE * 16];
__device__ float   g_h[(size_t)NNODE * HDIM];  // final layer-3 output (fp32)
__device__ float   g_pool[NGRAPH * HDIM];
__device__ float   g_cntg[NGRAPH];
__device__ int     g_is64;

// ---------------- init + dtype detect (fused, fully parallel) ----------------
__global__ void init_kernel(const void* ei) {
    int i = blockIdx.x * blockDim.x + threadIdx.x;
    if (i < NNODE) {
        g_deg[i] = 1.0f;   // self-loop weight 1
        g_cntD[i] = 0;
    }
    if (i < NGRAPH * HDIM) g_pool[i] = 0.0f;
    if (i < NGRAPH) g_cntg[i] = 0.0f;
    // warp 0 of block 0: parallel int64-vs-int32 detection.
    if (blockIdx.x == 0 && threadIdx.x < 32) {
        const long long* p = (const long long*)ei;
        int bad = 0;
        #pragma unroll
        for (int k = 0; k < 4; k++) {
            long long v = p[(threadIdx.x * 4 + k) * 5 + 1];
            if (v < 0 || v >= NNODE) bad = 1;
        }
        unsigned m = __ballot_sync(0xffffffffu, bad);
        if (threadIdx.x == 0) g_is64 = (m == 0u);
    }
}

// ---------------- histogram of destinations + weighted degree (x4 vec) ------
__global__ void hist_kernel(const void* ei, const float* __restrict__ ew) {
    int t = blockIdx.x * blockDim.x + threadIdx.x;   // 0 .. NEDGE/4-1
    if (t >= NEDGE / 4) return;
    int c0, c1, c2, c3;
    if (g_is64) {
        const longlong2* p = (const longlong2*)((const long long*)ei + NEDGE) + (size_t)t * 2;
        longlong2 a = p[0], b = p[1];
        c0 = (int)a.x; c1 = (int)a.y; c2 = (int)b.x; c3 = (int)b.y;
    } else {
        int4 v = ((const int4*)((const int*)ei + NEDGE))[t];
        c0 = v.x; c1 = v.y; c2 = v.z; c3 = v.w;
    }
    float4 w = ((const float4*)ew)[t];
    atomicAdd(&g_cntD[c0], 1); atomicAdd(&g_deg[c0], w.x);
    atomicAdd(&g_cntD[c1], 1); atomicAdd(&g_deg[c1], w.y);
    atomicAdd(&g_cntD[c2], 1); atomicAdd(&g_deg[c2], w.z);
    atomicAdd(&g_cntD[c3], 1); atomicAdd(&g_deg[c3], w.w);
}

// ---------------- three-phase parallel exclusive scan ----------------
__global__ void scanA_kernel() {       // per-block sums of 256 counts
    __shared__ int ws[8];
    int b = blockIdx.x, tid = threadIdx.x;
    int i = b * 256 + tid;
    int v = (i < NNODE) ? g_cntD[i] : 0;
    int lane = tid & 31, wid = tid >> 5;
    int s = v;
    #pragma unroll
    for (int o = 16; o > 0; o >>= 1) s += __shfl_down_sync(0xffffffffu, s, o);
    if (lane == 0) ws[wid] = s;
    __syncthreads();
    if (tid == 0) {
        int tot = 0;
        #pragma unroll
        for (int k = 0; k < 8; k++) tot += ws[k];
        g_blkSum[b] = tot;
    }
}

__global__ void scanB_kernel() {       // 1-block exclusive scan of NBLK sums
    __shared__ int ws[16];
    int tid = threadIdx.x;             // 512 threads
    int lane = tid & 31, wid = tid >> 5;
    int v = (tid < NBLK) ? g_blkSum[tid] : 0;
    int x = v;
    #pragma unroll
    for (int o = 1; o < 32; o <<= 1) {
        int y = __shfl_up_sync(0xffffffffu, x, o);
        if (lane >= o) x += y;
    }
    if (lane == 31) ws[wid] = x;
    __syncthreads();
    if (wid == 0 && lane < 16) {
        int s = ws[lane];
        #pragma unroll
        for (int o = 1; o < 16; o <<= 1) {
            int y = __shfl_up_sync(0x0000ffffu, s, o);
            if (lane >= o) s += y;
        }
        ws[lane] = s;
    }
    __syncthreads();
    int off = (wid > 0) ? ws[wid - 1] : 0;
    if (tid < NBLK) g_blkOff[tid] = x - v + off;
    if (tid == 0) g_ptrD[NNODE] = ws[15];
}

__global__ void scanC_kernel() {       // local scan + offset; also dinv + cnt reset
    __shared__ int ws[8];
    int b = blockIdx.x, tid = threadIdx.x;
    int i = b * 256 + tid;
    int v = (i < NNODE) ? g_cntD[i] : 0;
    int lane = tid & 31, wid = tid >> 5;
    int x = v;
    #pragma unroll
    for (int o = 1; o < 32; o <<= 1) {
        int y = __shfl_up_sync(0xffffffffu, x, o);
        if (lane >= o) x += y;
    }
    if (lane == 31) ws[wid] = x;
    __syncthreads();
    if (wid == 0 && lane < 8) {
        int s = ws[lane];
        #pragma unroll
        for (int o = 1; o < 8; o <<= 1) {
            int y = __shfl_up_sync(0x000000ffu, s, o);
            if (lane >= o) s += y;
        }
        ws[lane] = s;
    }
    __syncthreads();
    int woff = (wid > 0) ? ws[wid - 1] : 0;
    if (i < NNODE) {
        g_ptrD[i] = g_blkOff[b] + woff + x - v;
        g_cntD[i] = 0;
        g_dinv[i] = rsqrtf(g_deg[i]);   // deg >= 1 always
    }
}

// ---------------- fill CSR-by-destination, packed (src, w) ----------------
__global__ void fill_kernel(const void* ei, const float* __restrict__ ew) {
    int t = blockIdx.x * blockDim.x + threadIdx.x;   // 0 .. NEDGE/4-1
    if (t >= NEDGE / 4) return;
    int r[4], c[4];
    if (g_is64) {
        const longlong2* pr = (const longlong2*)((const long long*)ei) + (size_t)t * 2;
        const longlong2* pc = (const longlong2*)((const long long*)ei + NEDGE) + (size_t)t * 2;
        longlong2 a = pr[0], b = pr[1];
        r[0] = (int)a.x; r[1] = (int)a.y; r[2] = (int)b.x; r[3] = (int)b.y;
        a = pc[0]; b = pc[1];
        c[0] = (int)a.x; c[1] = (int)a.y; c[2] = (int)b.x; c[3] = (int)b.y;
    } else {
        int4 v = ((const int4*)((const int*)ei))[t];
        r[0] = v.x; r[1] = v.y; r[2] = v.z; r[3] = v.w;
        v = ((const int4*)((const int*)ei + NEDGE))[t];
        c[0] = v.x; c[1] = v.y; c[2] = v.z; c[3] = v.w;
    }
    float4 w4 = ((const float4*)ew)[t];
    float wv[4] = {w4.x, w4.y, w4.z, w4.w};
    #pragma unroll
    for (int k = 0; k < 4; k++) {
        float nw = g_dinv[r[k]] * wv[k] * g_dinv[c[k]];
        int pos = g_ptrD[c[k]] + atomicAdd(&g_cntD[c[k]], 1);
        g_eD[pos] = make_int2(r[k], __float_as_int(nw));
    }
}

// ---------------- GEMM1: t = x[N,128] @ W1[128,32], fp16 output ----------------
__global__ void gemm1_kernel(const float* __restrict__ A, const float* __restrict__ W,
                             __half2* __restrict__ out16) {
    constexpr int K = FIN;
    constexpr int PAD = 4;
    __shared__ float sW[K * 32];
    __shared__ float sA[64 * (K + PAD)];
    int tid = threadIdx.x;        // 256 threads
    int rb = blockIdx.x * 64;

    for (int i = tid; i < K * 8; i += 256)
        ((float4*)sW)[i] = ((const float4*)W)[i];

    int tc = tid & 7;             // col group (4 cols)
    int trp = tid >> 3;           // 0..31
    int r0 = trp * 2, r1 = r0 + 1;
    float acc[2][4] = {};

    for (int i = tid; i < 64 * K / 4; i += 256) {
        int r = i / (K / 4);
        int c4 = i % (K / 4);
        float4 v = make_float4(0.f, 0.f, 0.f, 0.f);
        if (rb + r < NNODE)
            v = *(const float4*)(A + (size_t)(rb + r) * K + c4 * 4);
        *(float4*)(sA + r * (K + PAD) + c4 * 4) = v;
    }
    __syncthreads();
    #pragma unroll 8
    for (int k = 0; k < K; k++) {
        float a0 = sA[r0 * (K + PAD) + k];
        float a1 = sA[r1 * (K + PAD) + k];
        float4 w = ((const float4*)sW)[k * 8 + tc];
        acc[0][0] += a0 * w.x; acc[0][1] += a0 * w.y;
        acc[0][2] += a0 * w.z; acc[0][3] += a0 * w.w;
        acc[1][0] += a1 * w.x; acc[1][1] += a1 * w.y;
        acc[1][2] += a1 * w.z; acc[1][3] += a1 * w.w;
    }
    #pragma unroll
    for (int rr = 0; rr < 2; rr++) {
        int r = rb + r0 + rr;
        if (r < NNODE) {
            out16[(size_t)r * 16 + tc * 2]     = __floats2half2_rn(acc[rr][0], acc[rr][1]);
            out16[(size_t)r * 16 + tc * 2 + 1] = __floats2half2_rn(acc[rr][2], acc[rr][3]);
        }
    }
}

// ---------------- aggregation: warp/node, 2 edges per iter, fused epilogue --
// MODE 0: h = relu(agg + bias); write t_next = h @ Wn as fp16 to tout16
// MODE 1: write agg + bias (no relu) as fp32 to hout
template <int MODE>
__global__ void agg_kernel(const __half2* __restrict__ tin,
                           const float* __restrict__ bias,
                           const float* __restrict__ Wn,
                           __half2* __restrict__ tout16,
                           float* __restrict__ hout) {
    __shared__ int2  s_e[8][32];
    __shared__ float s_row[8][32];
    int warp = threadIdx.x >> 5, lane = threadIdx.x & 31;
    int w = blockIdx.x * 8 + warp;

    float wcol[32];
    if (MODE == 0) {
        #pragma unroll
        for (int f = 0; f < 32; f++) wcol[f] = Wn[f * 32 + lane];
    }
    if (w >= NNODE) return;

    int p0 = g_ptrD[w], p1 = g_ptrD[w + 1];
    int el = lane >> 4, fp = lane & 15;
    float2 acc = make_float2(0.f, 0.f);
    float dv = g_dinv[w];
    if (el == 0) {                       // self-loop on lower half-warp
        float2 f2 = __half22float2(__ldg(&tin[(size_t)w * 16 + fp]));
        float s = dv * dv;
        acc.x = s * f2.x; acc.y = s * f2.y;
    }
    for (int p = p0; p < p1; p += 32) {
        int e = p + lane;
        s_e[warp][lane] = (e < p1) ? g_eD[e] : make_int2(0, 0);
        __syncwarp();
        int cnt = min(32, p1 - p);
        for (int j = 0; 2 * j < cnt; j++) {
            int2 sv = s_e[warp][2 * j + el];
            float ww = __int_as_float(sv.y);
            if (ww != 0.f) {
                float2 f2 = __half22float2(__ldg(&tin[(size_t)sv.x * 16 + fp]));
                acc.x += ww * f2.x; acc.y += ww * f2.y;
            }
        }
        __syncwarp();
    }
    // combine the two edge-halves
    acc.x += __shfl_down_sync(0xffffffffu, acc.x, 16);
    acc.y += __shfl_down_sync(0xffffffffu, acc.y, 16);
    if (el == 0) {
        acc.x += bias[2 * fp]; acc.y += bias[2 * fp + 1];
        if (MODE == 0) { acc.x = fmaxf(acc.x, 0.f); acc.y = fmaxf(acc.y, 0.f); }
        if (MODE == 1) {
            ((float2*)hout)[(size_t)w * 16 + fp] = acc;
        } else {
            s_row[warp][2 * fp] = acc.x;
            s_row[warp][2 * fp + 1] = acc.y;
        }
    }
    if (MODE == 0) {
        __syncwarp();
        float o = 0.f;
        #pragma unroll
        for (int f = 0; f < 32; f++) o += s_row[warp][f] * wcol[f];
        float oo = __shfl_down_sync(0xffffffffu, o, 1);
        if ((lane & 1) == 0)
            tout16[(size_t)w * 16 + (lane >> 1)] = __floats2half2_rn(o, oo);
    }
}

// ---------------- mean pool (batch is sorted) ----------------
__global__ void pool_kernel(const float* __restrict__ h, const void* batch) {
    int gtid = blockIdx.x * blockDim.x + threadIdx.x;
    int w = gtid >> 5, lane = gtid & 31;
    int n0 = w * 32;
    if (n0 >= NNODE) return;
    int is64 = g_is64;
    int n1 = (n0 + 32 < NNODE) ? n0 + 32 : NNODE;
    float acc = 0.f; int curg = -1; int run = 0;
    for (int i = n0; i < n1; i++) {
        int gg = is64 ? (int)((const long long*)batch)[i] : ((const int*)batch)[i];
        if (gg != curg) {
            if (curg >= 0) {
                atomicAdd(&g_pool[curg * 32 + lane], acc);
                if (lane == 0) atomicAdd(&g_cntg[curg], (float)run);
            }
            curg = gg; acc = 0.f; run = 0;
        }
        acc += h[(size_t)i * 32 + lane];
        run++;
    }
    if (curg >= 0) {
        atomicAdd(&g_pool[curg * 32 + lane], acc);
        if (lane == 0) atomicAdd(&g_cntg[curg], (float)run);
    }
}

// ---------------- tiny MLP head, single block, smem-staged weights ----------
__global__ void mlp_kernel(const float* __restrict__ Wm0, const float* __restrict__ bm0,
                           const float* __restrict__ Wm1, const float* __restrict__ bm1,
                           const float* __restrict__ Wout, const float* __restrict__ bout,
                           float* __restrict__ out) {
    __shared__ float sg[NGRAPH * HDIM];
    __shared__ float sm0[NGRAPH * MHDIM];
    __shared__ float sm1[NGRAPH * MHDIM];
    __shared__ float sW0[HDIM * MHDIM];
    __shared__ float sW1[MHDIM * MHDIM];
    __shared__ float sWo[MHDIM * NCLS];
    int tid = threadIdx.x;      // 256
    for (int i = tid; i < HDIM * MHDIM; i += 256) sW0[i] = Wm0[i];
    for (int i = tid; i < MHDIM * MHDIM; i += 256) sW1[i] = Wm1[i];
    for (int i = tid; i < MHDIM * NCLS; i += 256) sWo[i] = Wout[i];
    for (int i = tid; i < NGRAPH * HDIM; i += 256) {
        int gg = i / HDIM;
        sg[i] = g_pool[i] / fmaxf(g_cntg[gg], 1.0f);
    }
    __syncthreads();
    for (int i = tid; i < NGRAPH * MHDIM; i += 256) {
        int gg = i / MHDIM, j = i % MHDIM;
        float s = bm0[j];
        #pragma unroll
        for (int f = 0; f < HDIM; f++) s += sg[gg * HDIM + f] * sW0[f * MHDIM + j];
        sm0[i] = fmaxf(s, 0.f);
    }
    __syncthreads();
    for (int i = tid; i < NGRAPH * MHDIM; i += 256) {
        int gg = i / MHDIM, j = i % MHDIM;
        float s = bm1[j];
        #pragma unroll
        for (int f = 0; f < MHDIM; f++) s += sm0[gg * MHDIM + f] * sW1[f * MHDIM + j];
        sm1[i] = fmaxf(s, 0.f);
    }
    __syncthreads();
    for (int i = tid; i < NGRAPH * NCLS; i += 256) {
        int gg = i / NCLS, cc = i % NCLS;
        float s = bout[cc];
        #pragma unroll
        for (int j = 0; j < MHDIM; j++) s += sm1[gg * MHDIM + j] * sWo[j * NCLS + cc];
        out[i] = s;
    }
}

// ---------------- launch ----------------
extern "C" void kernel_launch(void* const* d_in, const int* in_sizes, int n_in,
                              void* d_out, int out_size) {
    const float* x    = (const float*)d_in[0];
    const void*  ei   = d_in[1];
    const float* ew   = (const float*)d_in[2];
    const void*  batch= d_in[3];
    const float* W1   = (const float*)d_in[4];
    const float* b1   = (const float*)d_in[5];
    const float* W2   = (const float*)d_in[6];
    const float* b2   = (const float*)d_in[7];
    const float* W3   = (const float*)d_in[8];
    const float* b3   = (const float*)d_in[9];
    const float* Wm0  = (const float*)d_in[10];
    const float* bm0  = (const float*)d_in[11];
    const float* Wm1  = (const float*)d_in[12];
    const float* bm1  = (const float*)d_in[13];
    const float* Wout = (const float*)d_in[14];
    const float* bout = (const float*)d_in[15];
    float* out = (float*)d_out;

    __half2 *tA, *tB; float* h_ptr;
    cudaGetSymbolAddress((void**)&tA, g_tA);
    cudaGetSymbolAddress((void**)&tB, g_tB);
    cudaGetSymbolAddress((void**)&h_ptr, g_h);

    const int EB4 = (NEDGE / 4 + 255) / 256;     // 3125
    const int NB  = NBLK;                         // 391
    const int GB  = (NNODE + 63) / 64;            // 1563
    const int AB  = (NNODE + 7) / 8;              // 12500 (8 warps/block, warp/node)

    init_kernel<<<NB, 256>>>(ei);
    hist_kernel<<<EB4, 256>>>(ei, ew);
    scanA_kernel<<<NB, 256>>>();
    scanB_kernel<<<1, 512>>>();
    scanC_kernel<<<NB, 256>>>();
    fill_kernel<<<EB4, 256>>>(ei, ew);

    gemm1_kernel<<<GB, 256>>>(x, W1, tA);                    // x@W1 -> tA (fp16)
    agg_kernel<0><<<AB, 256>>>(tA, b1, W2, tB, nullptr);     // agg+relu, @W2 -> tB
    agg_kernel<0><<<AB, 256>>>(tB, b2, W3, tA, nullptr);     // agg+relu, @W3 -> tA
    agg_kernel<1><<<AB, 256>>>(tA, b3, nullptr, nullptr, h_ptr); // agg+b3 -> h (fp32)

    pool_kernel<<<NB, 256>>>(h_ptr, batch);
    mlp_kernel<<<1, 256>>>(Wm0, bm0, Wm1, bm1, Wout, bout, out);
}

// round 6
// speedup vs baseline: 1.0611x; 1.0611x over previous
#include <cuda_runtime.h>
#include <cstdint>

#define NNODE 100000
#define NEDGE 3200000
#define FIN   128
#define HDIM  32
#define MHDIM 64
#define NCLS  10
#define NGRAPH 64
#define NBLK  ((NNODE + 255) / 256)   // 391

// ---------------- device scratch (static, no allocation) ----------------
__device__ float g_deg[NNODE];
__device__ float g_dinv[NNODE];
__device__ int   g_cntD[NNODE];
__device__ int   g_ptrD[NNODE + 1];
__device__ int2  g_eD[NEDGE];          // (src, weight-bits) packed
__device__ int   g_blkSum[NBLK];
__device__ int   g_blkOff[NBLK];
__device__ float g_tA[(size_t)NNODE * HDIM];   // feature tables, fp32, double-buffered
__device__ float g_tB[(size_t)NNODE * HDIM];
__device__ float g_h[(size_t)NNODE * HDIM];    // final layer-3 output
__device__ float g_pool[NGRAPH * HDIM];
__device__ float g_cntg[NGRAPH];
__device__ int   g_is64;

// ---------------- init + dtype detect (fused, fully parallel) ----------------
__global__ void init_kernel(const void* ei) {
    int i = blockIdx.x * blockDim.x + threadIdx.x;
    if (i < NNODE) {
        g_deg[i] = 1.0f;   // self-loop weight 1
        g_cntD[i] = 0;
    }
    if (i < NGRAPH * HDIM) g_pool[i] = 0.0f;
    if (i < NGRAPH) g_cntg[i] = 0.0f;
    // warp 0 of block 0: parallel int64-vs-int32 detection.
    if (blockIdx.x == 0 && threadIdx.x < 32) {
        const long long* p = (const long long*)ei;
        int bad = 0;
        #pragma unroll
        for (int k = 0; k < 4; k++) {
            long long v = p[(threadIdx.x * 4 + k) * 5 + 1];
            if (v < 0 || v >= NNODE) bad = 1;
        }
        unsigned m = __ballot_sync(0xffffffffu, bad);
        if (threadIdx.x == 0) g_is64 = (m == 0u);
    }
}

// ---------------- histogram of destinations + weighted degree (x4 vec) ------
__global__ void hist_kernel(const void* ei, const float* __restrict__ ew) {
    int t = blockIdx.x * blockDim.x + threadIdx.x;   // 0 .. NEDGE/4-1
    if (t >= NEDGE / 4) return;
    int c0, c1, c2, c3;
    if (g_is64) {
        const longlong2* p = (const longlong2*)((const long long*)ei + NEDGE) + (size_t)t * 2;
        longlong2 a = p[0], b = p[1];
        c0 = (int)a.x; c1 = (int)a.y; c2 = (int)b.x; c3 = (int)b.y;
    } else {
        int4 v = ((const int4*)((const int*)ei + NEDGE))[t];
        c0 = v.x; c1 = v.y; c2 = v.z; c3 = v.w;
    }
    float4 w = ((const float4*)ew)[t];
    atomicAdd(&g_cntD[c0], 1); atomicAdd(&g_deg[c0], w.x);
    atomicAdd(&g_cntD[c1], 1); atomicAdd(&g_deg[c1], w.y);
    atomicAdd(&g_cntD[c2], 1); atomicAdd(&g_deg[c2], w.z);
    atomicAdd(&g_cntD[c3], 1); atomicAdd(&g_deg[c3], w.w);
}

// ---------------- three-phase parallel exclusive scan ----------------
__global__ void scanA_kernel() {       // per-block sums of 256 counts
    __shared__ int ws[8];
    int b = blockIdx.x, tid = threadIdx.x;
    int i = b * 256 + tid;
    int v = (i < NNODE) ? g_cntD[i] : 0;
    int lane = tid & 31, wid = tid >> 5;
    int s = v;
    #pragma unroll
    for (int o = 16; o > 0; o >>= 1) s += __shfl_down_sync(0xffffffffu, s, o);
    if (lane == 0) ws[wid] = s;
    __syncthreads();
    if (tid == 0) {
        int tot = 0;
        #pragma unroll
        for (int k = 0; k < 8; k++) tot += ws[k];
        g_blkSum[b] = tot;
    }
}

__global__ void scanB_kernel() {       // 1-block exclusive scan of NBLK sums
    __shared__ int ws[16];
    int tid = threadIdx.x;             // 512 threads
    int lane = tid & 31, wid = tid >> 5;
    int v = (tid < NBLK) ? g_blkSum[tid] : 0;
    int x = v;
    #pragma unroll
    for (int o = 1; o < 32; o <<= 1) {
        int y = __shfl_up_sync(0xffffffffu, x, o);
        if (lane >= o) x += y;
    }
    if (lane == 31) ws[wid] = x;
    __syncthreads();
    if (wid == 0 && lane < 16) {
        int s = ws[lane];
        #pragma unroll
        for (int o = 1; o < 16; o <<= 1) {
            int y = __shfl_up_sync(0x0000ffffu, s, o);
            if (lane >= o) s += y;
        }
        ws[lane] = s;
    }
    __syncthreads();
    int off = (wid > 0) ? ws[wid - 1] : 0;
    if (tid < NBLK) g_blkOff[tid] = x - v + off;
    if (tid == 0) g_ptrD[NNODE] = ws[15];
}

__global__ void scanC_kernel() {       // local scan + offset; also dinv + cnt reset
    __shared__ int ws[8];
    int b = blockIdx.x, tid = threadIdx.x;
    int i = b * 256 + tid;
    int v = (i < NNODE) ? g_cntD[i] : 0;
    int lane = tid & 31, wid = tid >> 5;
    int x = v;
    #pragma unroll
    for (int o = 1; o < 32; o <<= 1) {
        int y = __shfl_up_sync(0xffffffffu, x, o);
        if (lane >= o) x += y;
    }
    if (lane == 31) ws[wid] = x;
    __syncthreads();
    if (wid == 0 && lane < 8) {
        int s = ws[lane];
        #pragma unroll
        for (int o = 1; o < 8; o <<= 1) {
            int y = __shfl_up_sync(0x000000ffu, s, o);
            if (lane >= o) s += y;
        }
        ws[lane] = s;
    }
    __syncthreads();
    int woff = (wid > 0) ? ws[wid - 1] : 0;
    if (i < NNODE) {
        g_ptrD[i] = g_blkOff[b] + woff + x - v;
        g_cntD[i] = 0;
        g_dinv[i] = rsqrtf(g_deg[i]);   // deg >= 1 always
    }
}

// ---------------- fill CSR-by-destination, packed (src, w) ----------------
__global__ void fill_kernel(const void* ei, const float* __restrict__ ew) {
    int t = blockIdx.x * blockDim.x + threadIdx.x;   // 0 .. NEDGE/4-1
    if (t >= NEDGE / 4) return;
    int r[4], c[4];
    if (g_is64) {
        const longlong2* pr = (const longlong2*)((const long long*)ei) + (size_t)t * 2;
        const longlong2* pc = (const longlong2*)((const long long*)ei + NEDGE) + (size_t)t * 2;
        longlong2 a = pr[0], b = pr[1];
        r[0] = (int)a.x; r[1] = (int)a.y; r[2] = (int)b.x; r[3] = (int)b.y;
        a = pc[0]; b = pc[1];
        c[0] = (int)a.x; c[1] = (int)a.y; c[2] = (int)b.x; c[3] = (int)b.y;
    } else {
        int4 v = ((const int4*)((const int*)ei))[t];
        r[0] = v.x; r[1] = v.y; r[2] = v.z; r[3] = v.w;
        v = ((const int4*)((const int*)ei + NEDGE))[t];
        c[0] = v.x; c[1] = v.y; c[2] = v.z; c[3] = v.w;
    }
    float4 w4 = ((const float4*)ew)[t];
    float wv[4] = {w4.x, w4.y, w4.z, w4.w};
    #pragma unroll
    for (int k = 0; k < 4; k++) {
        float nw = g_dinv[r[k]] * wv[k] * g_dinv[c[k]];
        int pos = g_ptrD[c[k]] + atomicAdd(&g_cntD[c[k]], 1);
        g_eD[pos] = make_int2(r[k], __float_as_int(nw));
    }
}

// ---------------- GEMM1: t = x[N,128] @ W1[128,32] ----------------
__global__ void gemm1_kernel(const float* __restrict__ A, const float* __restrict__ W,
                             float* __restrict__ out) {
    constexpr int K = FIN;
    constexpr int PAD = 4;
    __shared__ float sW[K * 32];
    __shared__ float sA[64 * (K + PAD)];
    int tid = threadIdx.x;        // 256 threads
    int rb = blockIdx.x * 64;

    for (int i = tid; i < K * 8; i += 256)
        ((float4*)sW)[i] = ((const float4*)W)[i];

    int tc = tid & 7;             // col group (4 cols)
    int trp = tid >> 3;           // 0..31
    int r0 = trp * 2, r1 = r0 + 1;
    float acc[2][4] = {};

    for (int i = tid; i < 64 * K / 4; i += 256) {
        int r = i / (K / 4);
        int c4 = i % (K / 4);
        float4 v = make_float4(0.f, 0.f, 0.f, 0.f);
        if (rb + r < NNODE)
            v = *(const float4*)(A + (size_t)(rb + r) * K + c4 * 4);
        *(float4*)(sA + r * (K + PAD) + c4 * 4) = v;
    }
    __syncthreads();
    #pragma unroll 8
    for (int k = 0; k < K; k++) {
        float a0 = sA[r0 * (K + PAD) + k];
        float a1 = sA[r1 * (K + PAD) + k];
        float4 w = ((const float4*)sW)[k * 8 + tc];
        acc[0][0] += a0 * w.x; acc[0][1] += a0 * w.y;
        acc[0][2] += a0 * w.z; acc[0][3] += a0 * w.w;
        acc[1][0] += a1 * w.x; acc[1][1] += a1 * w.y;
        acc[1][2] += a1 * w.z; acc[1][3] += a1 * w.w;
    }
    #pragma unroll
    for (int rr = 0; rr < 2; rr++) {
        int r = rb + r0 + rr;
        if (r < NNODE) {
            float4 v = make_float4(acc[rr][0], acc[rr][1], acc[rr][2], acc[rr][3]);
            *(float4*)(out + (size_t)r * 32 + tc * 4) = v;
        }
    }
}

// ---------------- aggregation: warp/node, 4 edges in flight, fused epilogue --
// lane = (edge-group g = lane>>3, feature-quad q = lane&7)
// MODE 0: h = relu(agg + bias); write t_next = h @ Wn to tout
// MODE 1: write agg + bias (no relu) to hout
template <int MODE>
__global__ void agg_kernel(const float* __restrict__ tin,
                           const float* __restrict__ bias,
                           const float* __restrict__ Wn,
                           float* __restrict__ tout,
                           float* __restrict__ hout) {
    __shared__ float s_row[8][32];
    int warp = threadIdx.x >> 5, lane = threadIdx.x & 31;
    int w = blockIdx.x * 8 + warp;
    int q = lane & 7, g = lane >> 3;

    float wcol[32];
    if (MODE == 0) {
        #pragma unroll
        for (int f = 0; f < 32; f++) wcol[f] = Wn[f * 32 + lane];
    }
    if (w >= NNODE) return;

    const float4* tin4 = (const float4*)tin;
    int p0 = g_ptrD[w], p1 = g_ptrD[w + 1];
    float4 acc = make_float4(0.f, 0.f, 0.f, 0.f);
    if (g == 0) {                         // self-loop on edge-group 0
        float dv = g_dinv[w];
        float4 f4 = __ldg(&tin4[(size_t)w * 8 + q]);
        float s = dv * dv;
        acc.x = s * f4.x; acc.y = s * f4.y; acc.z = s * f4.z; acc.w = s * f4.w;
    }
    // each edge-group walks edges p0+g, p0+g+4, ... : 4 gathers in flight/warp
    for (int p = p0 + g; p < p1; p += 4) {
        int2 ev = __ldg(&g_eD[p]);        // 8-lane broadcast
        float ww = __int_as_float(ev.y);
        float4 f4 = __ldg(&tin4[(size_t)ev.x * 8 + q]);
        acc.x += ww * f4.x; acc.y += ww * f4.y;
        acc.z += ww * f4.z; acc.w += ww * f4.w;
    }
    // reduce across the 4 edge-groups (lanes q, q+8, q+16, q+24)
    #pragma unroll
    for (int o = 16; o >= 8; o >>= 1) {
        acc.x += __shfl_down_sync(0xffffffffu, acc.x, o);
        acc.y += __shfl_down_sync(0xffffffffu, acc.y, o);
        acc.z += __shfl_down_sync(0xffffffffu, acc.z, o);
        acc.w += __shfl_down_sync(0xffffffffu, acc.w, o);
    }
    if (g == 0) {
        const float4* b4 = (const float4*)bias;
        float4 bb = __ldg(&b4[q]);
        acc.x += bb.x; acc.y += bb.y; acc.z += bb.z; acc.w += bb.w;
        if (MODE == 0) {
            acc.x = fmaxf(acc.x, 0.f); acc.y = fmaxf(acc.y, 0.f);
            acc.z = fmaxf(acc.z, 0.f); acc.w = fmaxf(acc.w, 0.f);
            *(float4*)&s_row[warp][q * 4] = acc;
        } else {
            ((float4*)hout)[(size_t)w * 8 + q] = acc;
        }
    }
    if (MODE == 0) {
        __syncwarp();
        float o = 0.f;
        #pragma unroll
        for (int f = 0; f < 32; f++) o += s_row[warp][f] * wcol[f];
        tout[(size_t)w * 32 + lane] = o;
    }
}

// ---------------- mean pool (batch is sorted) ----------------
__global__ void pool_kernel(const float* __restrict__ h, const void* batch) {
    int gtid = blockIdx.x * blockDim.x + threadIdx.x;
    int w = gtid >> 5, lane = gtid & 31;
    int n0 = w * 32;
    if (n0 >= NNODE) return;
    int is64 = g_is64;
    int n1 = (n0 + 32 < NNODE) ? n0 + 32 : NNODE;
    float acc = 0.f; int curg = -1; int run = 0;
    for (int i = n0; i < n1; i++) {
        int gg = is64 ? (int)((const long long*)batch)[i] : ((const int*)batch)[i];
        if (gg != curg) {
            if (curg >= 0) {
                atomicAdd(&g_pool[curg * 32 + lane], acc);
                if (lane == 0) atomicAdd(&g_cntg[curg], (float)run);
            }
            curg = gg; acc = 0.f; run = 0;
        }
        acc += h[(size_t)i * 32 + lane];
        run++;
    }
    if (curg >= 0) {
        atomicAdd(&g_pool[curg * 32 + lane], acc);
        if (lane == 0) atomicAdd(&g_cntg[curg], (float)run);
    }
}

// ---------------- tiny MLP head, single block, smem-staged weights ----------
__global__ void mlp_kernel(const float* __restrict__ Wm0, const float* __restrict__ bm0,
                           const float* __restrict__ Wm1, const float* __restrict__ bm1,
                           const float* __restrict__ Wout, const float* __restrict__ bout,
                           float* __restrict__ out) {
    __shared__ float sg[NGRAPH * HDIM];
    __shared__ float sm0[NGRAPH * MHDIM];
    __shared__ float sm1[NGRAPH * MHDIM];
    __shared__ float sW0[HDIM * MHDIM];
    __shared__ float sW1[MHDIM * MHDIM];
    __shared__ float sWo[MHDIM * NCLS];
    int tid = threadIdx.x;      // 256
    for (int i = tid; i < HDIM * MHDIM; i += 256) sW0[i] = Wm0[i];
    for (int i = tid; i < MHDIM * MHDIM; i += 256) sW1[i] = Wm1[i];
    for (int i = tid; i < MHDIM * NCLS; i += 256) sWo[i] = Wout[i];
    for (int i = tid; i < NGRAPH * HDIM; i += 256) {
        int gg = i / HDIM;
        sg[i] = g_pool[i] / fmaxf(g_cntg[gg], 1.0f);
    }
    __syncthreads();
    for (int i = tid; i < NGRAPH * MHDIM; i += 256) {
        int gg = i / MHDIM, j = i % MHDIM;
        float s = bm0[j];
        #pragma unroll
        for (int f = 0; f < HDIM; f++) s += sg[gg * HDIM + f] * sW0[f * MHDIM + j];
        sm0[i] = fmaxf(s, 0.f);
    }
    __syncthreads();
    for (int i = tid; i < NGRAPH * MHDIM; i += 256) {
        int gg = i / MHDIM, j = i % MHDIM;
        float s = bm1[j];
        #pragma unroll
        for (int f = 0; f < MHDIM; f++) s += sm0[gg * MHDIM + f] * sW1[f * MHDIM + j];
        sm1[i] = fmaxf(s, 0.f);
    }
    __syncthreads();
    for (int i = tid; i < NGRAPH * NCLS; i += 256) {
        int gg = i / NCLS, cc = i % NCLS;
        float s = bout[cc];
        #pragma unroll
        for (int j = 0; j < MHDIM; j++) s += sm1[gg * MHDIM + j] * sWo[j * NCLS + cc];
        out[i] = s;
    }
}

// ---------------- launch ----------------
extern "C" void kernel_launch(void* const* d_in, const int* in_sizes, int n_in,
                              void* d_out, int out_size) {
    const float* x    = (const float*)d_in[0];
    const void*  ei   = d_in[1];
    const float* ew   = (const float*)d_in[2];
    const void*  batch= d_in[3];
    const float* W1   = (const float*)d_in[4];
    const float* b1   = (const float*)d_in[5];
    const float* W2   = (const float*)d_in[6];
    const float* b2   = (const float*)d_in[7];
    const float* W3   = (const float*)d_in[8];
    const float* b3   = (const float*)d_in[9];
    const float* Wm0  = (const float*)d_in[10];
    const float* bm0  = (const float*)d_in[11];
    const float* Wm1  = (const float*)d_in[12];
    const float* bm1  = (const float*)d_in[13];
    const float* Wout = (const float*)d_in[14];
    const float* bout = (const float*)d_in[15];
    float* out = (float*)d_out;

    float *tA, *tB, *h_ptr;
    cudaGetSymbolAddress((void**)&tA, g_tA);
    cudaGetSymbolAddress((void**)&tB, g_tB);
    cudaGetSymbolAddress((void**)&h_ptr, g_h);

    const int EB4 = (NEDGE / 4 + 255) / 256;     // 3125
    const int NB  = NBLK;                         // 391
    const int GB  = (NNODE + 63) / 64;            // 1563
    const int AB  = (NNODE + 7) / 8;              // 12500 (8 warps/block, warp/node)

    init_kernel<<<NB, 256>>>(ei);
    hist_kernel<<<EB4, 256>>>(ei, ew);
    scanA_kernel<<<NB, 256>>>();
    scanB_kernel<<<1, 512>>>();
    scanC_kernel<<<NB, 256>>>();
    fill_kernel<<<EB4, 256>>>(ei, ew);

    gemm1_kernel<<<GB, 256>>>(x, W1, tA);                    // x@W1 -> tA
    agg_kernel<0><<<AB, 256>>>(tA, b1, W2, tB, nullptr);     // agg+relu, @W2 -> tB
    agg_kernel<0><<<AB, 256>>>(tB, b2, W3, tA, nullptr);     // agg+relu, @W3 -> tA
    agg_kernel<1><<<AB, 256>>>(tA, b3, nullptr, nullptr, h_ptr); // agg+b3 -> h

    pool_kernel<<<NB, 256>>>(h_ptr, batch);
    mlp_kernel<<<1, 256>>>(Wm0, bm0, Wm1, bm1, Wout, bout, out);
}